// round 16
// baseline (speedup 1.0000x reference)
#include <cuda_runtime.h>
#include <cuda_fp16.h>
#include <cstdint>
#include <math.h>

// Problem constants
#define Bq     8
#define Sq     16384          // 128*128
#define Eq     384
#define FFq    1536
#define MROWS  (Bq*Sq)        // 131072
#define EPSq   1e-5f
#define NQKV   1152

// ---------------- scratch (device globals; no allocation allowed) -----------
__device__ float2 g_stats[MROWS];                // LN1 mean/rstd
__device__ float2 g_sum2 [MROWS];                // LN2 raw (sum, sumsq), atomics
__device__ __half g_xh [(size_t)MROWS * Eq];     // fp16 copy of x (GEMM A)
__device__ __half g_qkv[(size_t)MROWS * NQKV];   // 302 MB
__device__ __half g_o  [(size_t)MROWS * Eq];     // 100 MB
__device__ __half g_x1h[(size_t)MROWS * Eq];     // fp16 residual stream
__device__ __half g_h  [(size_t)MROWS * FFq];    // 402 MB
__device__ __half g_wqkv[NQKV * Eq];             // g-scaled fp16 in_proj_w
__device__ __half g_w1p [FFq * Eq];              // g-scaled fp16 w1
__device__ __half g_owp [Eq * Eq];               // fp16 out_w
__device__ __half g_w2p [Eq * FFq];              // fp16 w2
__device__ float  g_c1q[NQKV], g_c2q[NQKV];
__device__ float  g_c1f[FFq],  g_c2f[FFq];

// ---------------- PTX helpers ------------------------------------------------
__device__ __forceinline__ uint32_t smem_u32(const void* p) {
    uint32_t a;
    asm("{ .reg .u64 t; cvta.to.shared.u64 t, %1; cvt.u32.u64 %0, t; }"
        : "=r"(a) : "l"(p));
    return a;
}
__device__ __forceinline__ void cp16(uint32_t s, const void* g) {
    asm volatile("cp.async.cg.shared.global [%0], [%1], 16;\n" :: "r"(s), "l"(g));
}
__device__ __forceinline__ void cp_commit() {
    asm volatile("cp.async.commit_group;\n" ::: "memory");
}
template<int N> __device__ __forceinline__ void cp_wait() {
    asm volatile("cp.async.wait_group %0;\n" :: "n"(N) : "memory");
}
// fp16 mma m16n8k16, f32 accumulate
__device__ __forceinline__ void mma_f16(float* c, const uint32_t* a, const uint32_t* b) {
    asm volatile(
        "mma.sync.aligned.m16n8k16.row.col.f32.f16.f16.f32 "
        "{%0,%1,%2,%3}, {%4,%5,%6,%7}, {%8,%9}, {%0,%1,%2,%3};\n"
        : "+f"(c[0]), "+f"(c[1]), "+f"(c[2]), "+f"(c[3])
        : "r"(a[0]), "r"(a[1]), "r"(a[2]), "r"(a[3]), "r"(b[0]), "r"(b[1]));
}
__device__ __forceinline__ void ldsm_x4(uint32_t* r, uint32_t addr) {
    asm volatile("ldmatrix.sync.aligned.m8n8.x4.shared.b16 {%0,%1,%2,%3}, [%4];"
                 : "=r"(r[0]), "=r"(r[1]), "=r"(r[2]), "=r"(r[3]) : "r"(addr));
}

// ------- fused LN1 stats + fp16 conversion of x + zero of LN2 sums ----------
__global__ void __launch_bounds__(256) stats_cvt_k(const float* __restrict__ X,
                                                   float2* __restrict__ st,
                                                   __half* __restrict__ Xh,
                                                   float2* __restrict__ sum2) {
    int gid = blockIdx.x * 256 + threadIdx.x;
    if (gid < MROWS) sum2[gid] = make_float2(0.f, 0.f);
    int row  = blockIdx.x * 8 + (threadIdx.x >> 5);
    int lane = threadIdx.x & 31;
    const float4* x = (const float4*)(X + (size_t)row * Eq);
    __half2* xh = (__half2*)(Xh + (size_t)row * Eq);
    float s = 0.f, ss = 0.f;
#pragma unroll
    for (int j = 0; j < 3; ++j) {
        float4 v = x[lane + 32 * j];
        s  += v.x + v.y + v.z + v.w;
        ss += v.x * v.x + v.y * v.y + v.z * v.z + v.w * v.w;
        xh[(lane + 32 * j) * 2]     = __floats2half2_rn(v.x, v.y);
        xh[(lane + 32 * j) * 2 + 1] = __floats2half2_rn(v.z, v.w);
    }
#pragma unroll
    for (int o = 16; o; o >>= 1) {
        s  += __shfl_xor_sync(0xffffffffu, s,  o);
        ss += __shfl_xor_sync(0xffffffffu, ss, o);
    }
    if (lane == 0) {
        float m   = s * (1.f / Eq);
        float var = ss * (1.f / Eq) - m * m;
        st[row] = make_float2(m, rsqrtf(var + EPSq));
    }
}

// ---- LN fold prep (both weight sets in one launch) --------------------------
__global__ void __launch_bounds__(128) prep_all_k(
    const float* __restrict__ Wa, const float* __restrict__ ba,
    const float* __restrict__ ga, const float* __restrict__ bea,
    __half* __restrict__ Wpa, float* __restrict__ c1a, float* __restrict__ c2a,
    const float* __restrict__ Wb, const float* __restrict__ bb,
    const float* __restrict__ gb, const float* __restrict__ beb,
    __half* __restrict__ Wpb, float* __restrict__ c1b, float* __restrict__ c2b)
{
    int n = blockIdx.x, t = threadIdx.x;
    const float *W, *bias, *g, *be; __half* Wp; float *c1, *c2;
    if (n < NQKV) { W = Wa; bias = ba; g = ga; be = bea; Wp = Wpa; c1 = c1a; c2 = c2a; }
    else { n -= NQKV; W = Wb; bias = bb; g = gb; be = beb; Wp = Wpb; c1 = c1b; c2 = c2b; }
    float s1 = 0.f, s2 = 0.f;
    for (int k = t; k < Eq; k += 128) {
        float w  = W[(size_t)n * Eq + k];
        __half hp = __float2half_rn(w * g[k]);
        Wp[(size_t)n * Eq + k] = hp;
        s1 += __half2float(hp);
        s2 += w * be[k];
    }
    __shared__ float r1[128], r2[128];
    r1[t] = s1; r2[t] = s2;
    __syncthreads();
    for (int o = 64; o; o >>= 1) {
        if (t < o) { r1[t] += r1[t + o]; r2[t] += r2[t + o]; }
        __syncthreads();
    }
    if (t == 0) { c1[n] = r1[0]; c2[n] = r2[0] + bias[n]; }
}

// ---- fp16 conversion of out_w and w2 in one launch --------------------------
#define OW_N (Eq * Eq)
#define W2_N (Eq * FFq)
__global__ void __launch_bounds__(256) cvt_both_k(const float* __restrict__ Wo,
                                                  __half* __restrict__ Wop,
                                                  const float* __restrict__ W2,
                                                  __half* __restrict__ W2p) {
    int i = blockIdx.x * 256 + threadIdx.x;
    if (i < OW_N) Wop[i] = __float2half_rn(Wo[i]);
    else if (i < OW_N + W2_N) W2p[i - OW_N] = __float2half_rn(W2[i - OW_N]);
}

// ---------------- fp16 mma.sync GEMM: C = A[M,K] @ W[N,K]^T (+epilogue) -----
// CTA tile 64(M) x 128(N), 8 warps of 32x32 -> 32 acc regs/thread,
// __launch_bounds__(256,3) -> 3 CTAs/SM (24 warps) for latency hiding.
// EPI 0: LN fold; 1: LN fold + erf-GELU; 2: + bias + residual.
// WH/WF: write half/float. SACC: accumulate per-row (sum, sumsq).
// SMODE: 1 = stats[] is raw (sum, sumsq). RH: fp16 residual.
#define BKq      32
#define ASTRIDE  40                        // halves; 80B row stride, 16B aligned
#define MT       64
#define NT       128
#define STAGE_H  ((MT + NT) * ASTRIDE)     // 7680 halves
#define STAGE_B  (STAGE_H * 2)             // 15360 bytes
#define SMEM_GEMM (2 * STAGE_B)            // double buffered (30720 B)

template<int EPI, bool WH, bool WF, bool SACC, int SMODE, bool RH>
__global__ void __launch_bounds__(256, 3)
tc_gemm(const __half* __restrict__ A, const __half* __restrict__ W,
        const float* __restrict__ bias, const float* __restrict__ resid,
        const __half* __restrict__ residh,
        const float2* __restrict__ stats, const float* __restrict__ c1,
        const float* __restrict__ c2, float* __restrict__ Cf,
        __half* __restrict__ Ch, float2* __restrict__ sums, int K, int N)
{
    extern __shared__ __half smemh[];
    const uint32_t sbase = smem_u32(smemh);
    const int tid = threadIdx.x;
    const int wid = tid >> 5, lane = tid & 31;
    const int g  = lane >> 2, tg = lane & 3;
    const int n0 = blockIdx.x * NT, m0 = blockIdx.y * MT;
    const int warp_m = wid >> 2, warp_n = wid & 3;       // 2 x 4 warp grid
    const int m_off = warp_m * 32, n_off = warp_n * 32;
    const int T = K / BKq;

    float acc[2][4][4];
#pragma unroll
    for (int mi = 0; mi < 2; ++mi)
#pragma unroll
        for (int ni = 0; ni < 4; ++ni)
#pragma unroll
            for (int j = 0; j < 4; ++j) acc[mi][ni][j] = 0.f;

    // ldmatrix per-lane base addresses (stage 0, k = 0); byte offsets
    const int lr8 = lane & 7;
    uint32_t baseA[2], baseB[2];
#pragma unroll
    for (int mi = 0; mi < 2; ++mi) {
        int row  = m_off + mi * 16 + ((lane >> 3) & 1) * 8 + lr8;
        int colh = (lane >> 4) * 8;
        baseA[mi] = sbase + (uint32_t)(row * ASTRIDE + colh) * 2;
    }
#pragma unroll
    for (int p = 0; p < 2; ++p) {
        int row  = n_off + p * 16 + ((lane >> 4) & 1) * 8 + lr8;
        int colh = ((lane >> 3) & 1) * 8;
        baseB[p] = sbase + (uint32_t)((MT + row) * ASTRIDE + colh) * 2;
    }

    // global loads per stage: A 64 rows x 64B (256 cp16, 1/thread);
    //                         B 128 rows x 64B (512 cp16, 2/thread)
    const int lrA = tid >> 2, chA = tid & 3;      // A row, 16B chunk
    const int lrB = tid >> 1, chB = tid & 1;      // B row, 32B half-row
    const char* Ag = (const char*)(A + (size_t)(m0 + lrA) * K) + chA * 16;
    const char* Bg = (const char*)(W + (size_t)(n0 + lrB) * K) + chB * 32;
    const uint32_t dA = sbase + (uint32_t)(lrA * ASTRIDE) * 2 + chA * 16;
    const uint32_t dB = sbase + (uint32_t)((MT + lrB) * ASTRIDE) * 2 + chB * 32;

    auto loadStage = [&](int buf, int kt) {
        const uint32_t so = (uint32_t)buf * STAGE_B;
        const char* ga = Ag + (size_t)kt * (BKq * 2);     // 64 bytes per k-tile
        const char* gb = Bg + (size_t)kt * (BKq * 2);
        cp16(dA + so, ga);
        cp16(dB + so,      gb);
        cp16(dB + so + 16, gb + 16);
    };

    loadStage(0, 0); cp_commit();

    int cur = 0;
    for (int t = 0; t < T; ++t) {
        if (t + 1 < T) loadStage(cur ^ 1, t + 1);
        cp_commit();
        cp_wait<1>();
        __syncthreads();

        const uint32_t so = (uint32_t)cur * STAGE_B;
#pragma unroll
        for (int ks = 0; ks < 2; ++ks) {
            const uint32_t ko = so + ks * 32;             // 16 halves = 32 bytes
            uint32_t a[2][4], b[4][2], tb[4];
#pragma unroll
            for (int mi = 0; mi < 2; ++mi)
                ldsm_x4(a[mi], baseA[mi] + ko);
#pragma unroll
            for (int p = 0; p < 2; ++p) {
                ldsm_x4(tb, baseB[p] + ko);
                b[2*p][0]   = tb[0]; b[2*p][1]   = tb[1];
                b[2*p+1][0] = tb[2]; b[2*p+1][1] = tb[3];
            }
#pragma unroll
            for (int mi = 0; mi < 2; ++mi)
#pragma unroll
                for (int ni = 0; ni < 4; ++ni)
                    mma_f16(acc[mi][ni], a[mi], b[ni]);
        }
        __syncthreads();
        cur ^= 1;
    }

    // ---------------- epilogue ----------------
    float c1v[8], c2v[8];
#pragma unroll
    for (int ni = 0; ni < 4; ++ni) {
        int n = n0 + n_off + ni * 8 + 2 * tg;
        if (EPI != 2) {
            c1v[ni * 2]     = c1[n];     c2v[ni * 2]     = c2[n];
            c1v[ni * 2 + 1] = c1[n + 1]; c2v[ni * 2 + 1] = c2[n + 1];
        } else {
            c2v[ni * 2]     = bias[n];
            c2v[ni * 2 + 1] = bias[n + 1];
        }
    }

#pragma unroll
    for (int mi = 0; mi < 2; ++mi) {
        const int r0 = m0 + m_off + mi * 16 + g;
        const int r1 = r0 + 8;
        float rr0 = 0.f, rm0 = 0.f, rr1 = 0.f, rm1 = 0.f;
        if (EPI != 2) {
            float2 s0 = stats[r0], s1 = stats[r1];
            if (SMODE == 1) {
                float m0v = s0.x * (1.f / Eq);
                float v0v = s0.y * (1.f / Eq) - m0v * m0v;
                float m1v = s1.x * (1.f / Eq);
                float v1v = s1.y * (1.f / Eq) - m1v * m1v;
                rr0 = rsqrtf(v0v + EPSq); rm0 = m0v * rr0;
                rr1 = rsqrtf(v1v + EPSq); rm1 = m1v * rr1;
            } else {
                rr0 = s0.y; rm0 = s0.x * s0.y;
                rr1 = s1.y; rm1 = s1.x * s1.y;
            }
        }
        float rs0 = 0.f, rq0 = 0.f, rs1 = 0.f, rq1 = 0.f;
#pragma unroll
        for (int ni = 0; ni < 4; ++ni) {
            const int n = n0 + n_off + ni * 8 + 2 * tg;
            float v0 = acc[mi][ni][0], v1 = acc[mi][ni][1];
            float v2 = acc[mi][ni][2], v3 = acc[mi][ni][3];
            if (EPI == 0 || EPI == 1) {
                v0 = rr0 * v0 - rm0 * c1v[ni * 2]     + c2v[ni * 2];
                v1 = rr0 * v1 - rm0 * c1v[ni * 2 + 1] + c2v[ni * 2 + 1];
                v2 = rr1 * v2 - rm1 * c1v[ni * 2]     + c2v[ni * 2];
                v3 = rr1 * v3 - rm1 * c1v[ni * 2 + 1] + c2v[ni * 2 + 1];
                if (EPI == 1) {
                    v0 = 0.5f * v0 * (1.f + erff(v0 * 0.70710678118654752f));
                    v1 = 0.5f * v1 * (1.f + erff(v1 * 0.70710678118654752f));
                    v2 = 0.5f * v2 * (1.f + erff(v2 * 0.70710678118654752f));
                    v3 = 0.5f * v3 * (1.f + erff(v3 * 0.70710678118654752f));
                }
            } else {
                if (RH) {
                    float2 ra = __half22float2(*(const __half2*)(residh + (size_t)r0 * N + n));
                    float2 rb = __half22float2(*(const __half2*)(residh + (size_t)r1 * N + n));
                    v0 += c2v[ni * 2] + ra.x;  v1 += c2v[ni * 2 + 1] + ra.y;
                    v2 += c2v[ni * 2] + rb.x;  v3 += c2v[ni * 2 + 1] + rb.y;
                } else {
                    const float2 ra = *(const float2*)(resid + (size_t)r0 * N + n);
                    const float2 rb = *(const float2*)(resid + (size_t)r1 * N + n);
                    v0 += c2v[ni * 2] + ra.x;  v1 += c2v[ni * 2 + 1] + ra.y;
                    v2 += c2v[ni * 2] + rb.x;  v3 += c2v[ni * 2 + 1] + rb.y;
                }
            }
            if (SACC) {
                rs0 += v0 + v1;           rq0 += v0 * v0 + v1 * v1;
                rs1 += v2 + v3;           rq1 += v2 * v2 + v3 * v3;
            }
            if (WF) {
                *(float2*)(Cf + (size_t)r0 * N + n) = make_float2(v0, v1);
                *(float2*)(Cf + (size_t)r1 * N + n) = make_float2(v2, v3);
            }
            if (WH) {
                *(__half2*)(Ch + (size_t)r0 * N + n) = __floats2half2_rn(v0, v1);
                *(__half2*)(Ch + (size_t)r1 * N + n) = __floats2half2_rn(v2, v3);
            }
        }
        if (SACC) {
#pragma unroll
            for (int o = 1; o <= 2; o <<= 1) {
                rs0 += __shfl_xor_sync(0xffffffffu, rs0, o);
                rq0 += __shfl_xor_sync(0xffffffffu, rq0, o);
                rs1 += __shfl_xor_sync(0xffffffffu, rs1, o);
                rq1 += __shfl_xor_sync(0xffffffffu, rq1, o);
            }
            if (tg == 0) {
                atomicAdd(&sums[r0].x, rs0);
                atomicAdd(&sums[r0].y, rq0);
                atomicAdd(&sums[r1].x, rs1);
                atomicAdd(&sums[r1].y, rq1);
            }
        }
    }
}

// ---------------- attention over batch axis (len 8) per (s, head) -----------
#define QSH 1160    // halves; 2320 B row stride
__global__ void __launch_bounds__(288) attn_k(const __half* __restrict__ qkv,
                                              __half* __restrict__ o) {
    __shared__ __half sq[8 * QSH];
    __shared__ float sc[8][64];
    const int s   = blockIdx.x;
    const int tid = threadIdx.x;

#pragma unroll
    for (int j = 0; j < 4; ++j) {            // 8 rows x 144 uint4 = 1152 loads
        int i = tid + j * 288;
        int b = i / 144, jj = i % 144;
        uint4 v = *(const uint4*)(qkv + ((size_t)(b * Sq + s)) * NQKV + jj * 8);
        *(uint4*)(sq + b * QSH + jj * 8) = v;
    }
    __syncthreads();

    const int h = tid >> 5, lane = tid & 31;
    if (h >= 8) return;
    const float scale = 0.14433756729740644f;   // 1/sqrt(48)

    {
        int idx0 = lane, idx1 = lane + 32;
        int b0 = idx0 >> 3, cc0 = idx0 & 7;
        int b1 = idx1 >> 3, cc1 = idx1 & 7;
        const __half2* q0 = (const __half2*)(sq + b0 * QSH + h * 48);
        const __half2* k0 = (const __half2*)(sq + cc0 * QSH + 384 + h * 48);
        const __half2* q1 = (const __half2*)(sq + b1 * QSH + h * 48);
        const __half2* k1 = (const __half2*)(sq + cc1 * QSH + 384 + h * 48);
        float s0 = 0.f, s1 = 0.f;
#pragma unroll
        for (int d2 = 0; d2 < 24; ++d2) {
            float2 qa = __half22float2(q0[d2]), ka = __half22float2(k0[d2]);
            s0 += qa.x * ka.x + qa.y * ka.y;
            float2 qb = __half22float2(q1[d2]), kb = __half22float2(k1[d2]);
            s1 += qb.x * kb.x + qb.y * kb.y;
        }
        sc[h][idx0] = s0 * scale;
        sc[h][idx1] = s1 * scale;
    }
    __syncwarp();

    if (lane < 8) {
        float e[8]; float mx = -1e30f;
#pragma unroll
        for (int c = 0; c < 8; ++c) { e[c] = sc[h][lane * 8 + c]; mx = fmaxf(mx, e[c]); }
        float sum = 0.f;
#pragma unroll
        for (int c = 0; c < 8; ++c) { e[c] = expf(e[c] - mx); sum += e[c]; }
        float inv = 1.f / sum;
#pragma unroll
        for (int c = 0; c < 8; ++c) sc[h][lane * 8 + c] = e[c] * inv;
    }
    __syncwarp();

#pragma unroll
    for (int j = 0; j < 3; ++j) {
        int e4 = lane + j * 32;
        int b = e4 / 12, d4 = e4 % 12;
        float a0 = 0.f, a1 = 0.f, a2 = 0.f, a3 = 0.f;
#pragma unroll
        for (int c = 0; c < 8; ++c) {
            float p = sc[h][b * 8 + c];
            const __half2* v = (const __half2*)(sq + c * QSH + 768 + h * 48 + d4 * 4);
            float2 f0 = __half22float2(v[0]);
            float2 f1 = __half22float2(v[1]);
            a0 += p * f0.x; a1 += p * f0.y; a2 += p * f1.x; a3 += p * f1.y;
        }
        __half2 o0 = __floats2half2_rn(a0, a1);
        __half2 o1 = __floats2half2_rn(a2, a3);
        __half2* dst = (__half2*)(o + ((size_t)(b * Sq + s)) * Eq + h * 48 + d4 * 4);
        dst[0] = o0; dst[1] = o1;
    }
}

// ---------------- launch -----------------------------------------------------
extern "C" void kernel_launch(void* const* d_in, const int* in_sizes, int n_in,
                              void* d_out, int out_size) {
    const float* x     = (const float*)d_in[0];
    const float* in_w  = (const float*)d_in[1];
    const float* in_b  = (const float*)d_in[2];
    const float* out_w = (const float*)d_in[3];
    const float* out_b = (const float*)d_in[4];
    const float* ln1g  = (const float*)d_in[5];
    const float* ln1b  = (const float*)d_in[6];
    const float* ln2g  = (const float*)d_in[7];
    const float* ln2b  = (const float*)d_in[8];
    const float* w1    = (const float*)d_in[9];
    const float* b1    = (const float*)d_in[10];
    const float* w2    = (const float*)d_in[11];
    const float* b2    = (const float*)d_in[12];
    float* out = (float*)d_out;

    float2 *stats, *sum2; float *c1q, *c2q, *c1f, *c2f;
    __half *xh, *qkv, *obuf, *x1h, *hbuf, *wqkv, *w1p, *owp, *w2p;
    cudaGetSymbolAddress((void**)&stats, g_stats);
    cudaGetSymbolAddress((void**)&sum2,  g_sum2);
    cudaGetSymbolAddress((void**)&xh,    g_xh);
    cudaGetSymbolAddress((void**)&qkv,   g_qkv);
    cudaGetSymbolAddress((void**)&obuf,  g_o);
    cudaGetSymbolAddress((void**)&x1h,   g_x1h);
    cudaGetSymbolAddress((void**)&hbuf,  g_h);
    cudaGetSymbolAddress((void**)&wqkv,  g_wqkv);
    cudaGetSymbolAddress((void**)&w1p,   g_w1p);
    cudaGetSymbolAddress((void**)&owp,   g_owp);
    cudaGetSymbolAddress((void**)&w2p,   g_w2p);
    cudaGetSymbolAddress((void**)&c1q,   g_c1q);
    cudaGetSymbolAddress((void**)&c2q,   g_c2q);
    cudaGetSymbolAddress((void**)&c1f,   g_c1f);
    cudaGetSymbolAddress((void**)&c2f,   g_c2f);

    cudaFuncSetAttribute((const void*)tc_gemm<0, true, false, false, 0, false>,
                         cudaFuncAttributeMaxDynamicSharedMemorySize, SMEM_GEMM);
    cudaFuncSetAttribute((const void*)tc_gemm<1, true, false, false, 1, false>,
                         cudaFuncAttributeMaxDynamicSharedMemorySize, SMEM_GEMM);
    cudaFuncSetAttribute((const void*)tc_gemm<2, true, false, true, 0, false>,
                         cudaFuncAttributeMaxDynamicSharedMemorySize, SMEM_GEMM);
    cudaFuncSetAttribute((const void*)tc_gemm<2, false, true, false, 0, true>,
                         cudaFuncAttributeMaxDynamicSharedMemorySize, SMEM_GEMM);

    // 0) fold LN1 into in_proj weights + LN2 into w1 (one launch)
    prep_all_k<<<NQKV + FFq, 128>>>(in_w, in_b, ln1g, ln1b, wqkv, c1q, c2q,
                                    w1,   b1,   ln2g, ln2b, w1p,  c1f, c2f);
    // 1) fp16-convert out_w + w2 (one launch)
    cvt_both_k<<<(OW_N + W2_N + 255) / 256, 256>>>(out_w, owp, w2, w2p);
    // 2) LN1 stats + x -> fp16 + zero LN2 sums
    stats_cvt_k<<<MROWS / 8, 256>>>(x, stats, xh, sum2);
    // 3) qkv = LN1(x) @ in_proj_w^T + in_proj_b   (LN folded, fp16 out)
    {
        dim3 g(NQKV / NT, MROWS / MT);
        tc_gemm<0, true, false, false, 0, false><<<g, 256, SMEM_GEMM>>>(
            xh, wqkv, nullptr, nullptr, nullptr, stats, c1q, c2q,
            nullptr, qkv, nullptr, Eq, NQKV);
    }
    // 4) batch-axis attention per (s, head)
    attn_k<<<Sq, 288>>>(qkv, obuf);
    // 5) x1h = fp16( x + o @ out_w^T + out_b ), accumulate LN2 sums
    {
        dim3 g(Eq / NT, MROWS / MT);
        tc_gemm<2, true, false, true, 0, false><<<g, 256, SMEM_GEMM>>>(
            obuf, owp, out_b, x, nullptr, nullptr, nullptr, nullptr,
            nullptr, x1h, sum2, Eq, Eq);
    }
    // 6) h = gelu( LN2(x1) @ w1^T + b1 )  (LN folded, stats from raw sums)
    {
        dim3 g(FFq / NT, MROWS / MT);
        tc_gemm<1, true, false, false, 1, false><<<g, 256, SMEM_GEMM>>>(
            x1h, w1p, nullptr, nullptr, nullptr, sum2, c1f, c2f,
            nullptr, hbuf, nullptr, Eq, FFq);
    }
    // 7) out = x1h + h @ w2^T + b2   (fp32 out, fp16 residual)
    {
        dim3 g(Eq / NT, MROWS / MT);
        tc_gemm<2, false, true, false, 0, true><<<g, 256, SMEM_GEMM>>>(
            hbuf, w2p, b2, nullptr, x1h, nullptr, nullptr, nullptr,
            out, nullptr, nullptr, FFq, Eq);
    }
}

// round 17
// speedup vs baseline: 1.1592x; 1.1592x over previous
#include <cuda_runtime.h>
#include <cuda_fp16.h>
#include <cstdint>
#include <math.h>

// Problem constants
#define Bq     8
#define Sq     16384          // 128*128
#define Eq     384
#define FFq    1536
#define MROWS  (Bq*Sq)        // 131072
#define EPSq   1e-5f
#define NQKV   1152

// ---------------- scratch (device globals; no allocation allowed) -----------
__device__ float2 g_stats[MROWS];                // LN1 mean/rstd
__device__ float2 g_sum2 [MROWS];                // LN2 raw (sum, sumsq), atomics
__device__ __half g_xh [(size_t)MROWS * Eq];     // fp16 copy of x (GEMM A)
__device__ __half g_qkv[(size_t)MROWS * NQKV];   // 302 MB
__device__ __half g_o  [(size_t)MROWS * Eq];     // 100 MB
__device__ __half g_x1h[(size_t)MROWS * Eq];     // fp16 residual stream
__device__ __half g_h  [(size_t)MROWS * FFq];    // 402 MB
__device__ __half g_wqkv[NQKV * Eq];             // g-scaled fp16 in_proj_w
__device__ __half g_w1p [FFq * Eq];              // g-scaled fp16 w1
__device__ __half g_owp [Eq * Eq];               // fp16 out_w
__device__ __half g_w2p [Eq * FFq];              // fp16 w2
__device__ float  g_c1q[NQKV], g_c2q[NQKV];
__device__ float  g_c1f[FFq],  g_c2f[FFq];

// ---------------- PTX helpers ------------------------------------------------
__device__ __forceinline__ uint32_t smem_u32(const void* p) {
    uint32_t a;
    asm("{ .reg .u64 t; cvta.to.shared.u64 t, %1; cvt.u32.u64 %0, t; }"
        : "=r"(a) : "l"(p));
    return a;
}
__device__ __forceinline__ void cp16(uint32_t s, const void* g) {
    asm volatile("cp.async.cg.shared.global [%0], [%1], 16;\n" :: "r"(s), "l"(g));
}
__device__ __forceinline__ void cp_commit() {
    asm volatile("cp.async.commit_group;\n" ::: "memory");
}
template<int N> __device__ __forceinline__ void cp_wait() {
    asm volatile("cp.async.wait_group %0;\n" :: "n"(N) : "memory");
}
// fp16 mma m16n8k16, f32 accumulate
__device__ __forceinline__ void mma_f16(float* c, const uint32_t* a, const uint32_t* b) {
    asm volatile(
        "mma.sync.aligned.m16n8k16.row.col.f32.f16.f16.f32 "
        "{%0,%1,%2,%3}, {%4,%5,%6,%7}, {%8,%9}, {%0,%1,%2,%3};\n"
        : "+f"(c[0]), "+f"(c[1]), "+f"(c[2]), "+f"(c[3])
        : "r"(a[0]), "r"(a[1]), "r"(a[2]), "r"(a[3]), "r"(b[0]), "r"(b[1]));
}
__device__ __forceinline__ void ldsm_x4(uint32_t* r, uint32_t addr) {
    asm volatile("ldmatrix.sync.aligned.m8n8.x4.shared.b16 {%0,%1,%2,%3}, [%4];"
                 : "=r"(r[0]), "=r"(r[1]), "=r"(r[2]), "=r"(r[3]) : "r"(addr));
}

// ------- fused LN1 stats + fp16 conversion of x + zero of LN2 sums ----------
__global__ void __launch_bounds__(256) stats_cvt_k(const float* __restrict__ X,
                                                   float2* __restrict__ st,
                                                   __half* __restrict__ Xh,
                                                   float2* __restrict__ sum2) {
    int gid = blockIdx.x * 256 + threadIdx.x;
    if (gid < MROWS) sum2[gid] = make_float2(0.f, 0.f);
    int row  = blockIdx.x * 8 + (threadIdx.x >> 5);
    int lane = threadIdx.x & 31;
    const float4* x = (const float4*)(X + (size_t)row * Eq);
    __half2* xh = (__half2*)(Xh + (size_t)row * Eq);
    float s = 0.f, ss = 0.f;
#pragma unroll
    for (int j = 0; j < 3; ++j) {
        float4 v = x[lane + 32 * j];
        s  += v.x + v.y + v.z + v.w;
        ss += v.x * v.x + v.y * v.y + v.z * v.z + v.w * v.w;
        xh[(lane + 32 * j) * 2]     = __floats2half2_rn(v.x, v.y);
        xh[(lane + 32 * j) * 2 + 1] = __floats2half2_rn(v.z, v.w);
    }
#pragma unroll
    for (int o = 16; o; o >>= 1) {
        s  += __shfl_xor_sync(0xffffffffu, s,  o);
        ss += __shfl_xor_sync(0xffffffffu, ss, o);
    }
    if (lane == 0) {
        float m   = s * (1.f / Eq);
        float var = ss * (1.f / Eq) - m * m;
        st[row] = make_float2(m, rsqrtf(var + EPSq));
    }
}

// ---- LN fold prep (both weight sets in one launch) --------------------------
__global__ void __launch_bounds__(128) prep_all_k(
    const float* __restrict__ Wa, const float* __restrict__ ba,
    const float* __restrict__ ga, const float* __restrict__ bea,
    __half* __restrict__ Wpa, float* __restrict__ c1a, float* __restrict__ c2a,
    const float* __restrict__ Wb, const float* __restrict__ bb,
    const float* __restrict__ gb, const float* __restrict__ beb,
    __half* __restrict__ Wpb, float* __restrict__ c1b, float* __restrict__ c2b)
{
    int n = blockIdx.x, t = threadIdx.x;
    const float *W, *bias, *g, *be; __half* Wp; float *c1, *c2;
    if (n < NQKV) { W = Wa; bias = ba; g = ga; be = bea; Wp = Wpa; c1 = c1a; c2 = c2a; }
    else { n -= NQKV; W = Wb; bias = bb; g = gb; be = beb; Wp = Wpb; c1 = c1b; c2 = c2b; }
    float s1 = 0.f, s2 = 0.f;
    for (int k = t; k < Eq; k += 128) {
        float w  = W[(size_t)n * Eq + k];
        __half hp = __float2half_rn(w * g[k]);
        Wp[(size_t)n * Eq + k] = hp;
        s1 += __half2float(hp);
        s2 += w * be[k];
    }
    __shared__ float r1[128], r2[128];
    r1[t] = s1; r2[t] = s2;
    __syncthreads();
    for (int o = 64; o; o >>= 1) {
        if (t < o) { r1[t] += r1[t + o]; r2[t] += r2[t + o]; }
        __syncthreads();
    }
    if (t == 0) { c1[n] = r1[0]; c2[n] = r2[0] + bias[n]; }
}

// ---- fp16 conversion of out_w and w2 in one launch --------------------------
#define OW_N (Eq * Eq)
#define W2_N (Eq * FFq)
__global__ void __launch_bounds__(256) cvt_both_k(const float* __restrict__ Wo,
                                                  __half* __restrict__ Wop,
                                                  const float* __restrict__ W2,
                                                  __half* __restrict__ W2p) {
    int i = blockIdx.x * 256 + threadIdx.x;
    if (i < OW_N) Wop[i] = __float2half_rn(Wo[i]);
    else if (i < OW_N + W2_N) W2p[i - OW_N] = __float2half_rn(W2[i - OW_N]);
}

// ---------------- fp16 mma.sync GEMM: C = A[M,K] @ W[N,K]^T (+epilogue) -----
// 128x128 CTA tile (R15 best), 4-stage cp.async ring, ONE barrier per stage.
// EPI 0: LN fold; 1: LN fold + erf-GELU; 2: + bias + residual.
// WH/WF: write half/float. SACC: accumulate per-row (sum, sumsq).
// SMODE: 1 = stats[] is raw (sum, sumsq). RH: fp16 residual.
#define BKq      32
#define ASTRIDE  40                        // halves; 80B row stride, 16B aligned
#define NSTG     4
#define STAGE_H  (2 * 128 * ASTRIDE)       // A + B halves per stage
#define STAGE_B  (STAGE_H * 2)             // 20480 bytes
#define SMEM_GEMM (NSTG * STAGE_B)         // 81920 bytes

template<int EPI, bool WH, bool WF, bool SACC, int SMODE, bool RH>
__global__ void __launch_bounds__(256, 2)
tc_gemm(const __half* __restrict__ A, const __half* __restrict__ W,
        const float* __restrict__ bias, const float* __restrict__ resid,
        const __half* __restrict__ residh,
        const float2* __restrict__ stats, const float* __restrict__ c1,
        const float* __restrict__ c2, float* __restrict__ Cf,
        __half* __restrict__ Ch, float2* __restrict__ sums, int K, int N)
{
    extern __shared__ __half smemh[];
    const uint32_t sbase = smem_u32(smemh);
    const int tid = threadIdx.x;
    const int wid = tid >> 5, lane = tid & 31;
    const int g  = lane >> 2, tg = lane & 3;
    const int n0 = blockIdx.x * 128, m0 = blockIdx.y * 128;
    const int warp_m = wid >> 2, warp_n = wid & 3;       // 2 x 4 warp grid
    const int m_off = warp_m * 64, n_off = warp_n * 32;
    const int T = K / BKq;

    float acc[4][4][4];
#pragma unroll
    for (int mi = 0; mi < 4; ++mi)
#pragma unroll
        for (int ni = 0; ni < 4; ++ni)
#pragma unroll
            for (int j = 0; j < 4; ++j) acc[mi][ni][j] = 0.f;

    // ldmatrix per-lane base addresses (stage 0, k = 0); byte offsets
    const int lr8 = lane & 7;
    uint32_t baseA[4], baseB[2];
#pragma unroll
    for (int mi = 0; mi < 4; ++mi) {
        int row  = m_off + mi * 16 + ((lane >> 3) & 1) * 8 + lr8;
        int colh = (lane >> 4) * 8;
        baseA[mi] = sbase + (uint32_t)(row * ASTRIDE + colh) * 2;
    }
#pragma unroll
    for (int p = 0; p < 2; ++p) {
        int row  = n_off + p * 16 + ((lane >> 4) & 1) * 8 + lr8;
        int colh = ((lane >> 3) & 1) * 8;
        baseB[p] = sbase + (uint32_t)((128 + row) * ASTRIDE + colh) * 2;
    }

    // global loads: row = tid>>1 (0..127), half = tid&1 -> 2 x 16B chunks each
    const int lr = tid >> 1, lh = tid & 1;
    const char* Ag = (const char*)(A + (size_t)(m0 + lr) * K) + lh * 32;
    const char* Bg = (const char*)(W + (size_t)(n0 + lr) * K) + lh * 32;
    const uint32_t dA = sbase + (uint32_t)(lr * ASTRIDE) * 2 + lh * 32;
    const uint32_t dB = dA + 128 * ASTRIDE * 2;

    auto loadStage = [&](int buf, int kt) {
        const uint32_t so = (uint32_t)buf * STAGE_B;
        const char* ga = Ag + (size_t)kt * (BKq * 2);     // 64 bytes per k-tile
        const char* gb = Bg + (size_t)kt * (BKq * 2);
#pragma unroll
        for (int c = 0; c < 2; ++c) {
            cp16(dA + so + c * 16, ga + c * 16);
            cp16(dB + so + c * 16, gb + c * 16);
        }
    };

    // prologue: fill NSTG-1 stages (one commit group each)
#pragma unroll
    for (int s = 0; s < NSTG - 1; ++s) {
        if (s < T) loadStage(s, s);
        cp_commit();
    }

    for (int t = 0; t < T; ++t) {
        cp_wait<NSTG - 2>();             // stage t data landed
        __syncthreads();                 // all warps done reading buf (t-1)%NSTG
        if (t + NSTG - 1 < T) loadStage((t + NSTG - 1) % NSTG, t + NSTG - 1);
        cp_commit();

        const uint32_t so = (uint32_t)(t % NSTG) * STAGE_B;
#pragma unroll
        for (int ks = 0; ks < 2; ++ks) {
            const uint32_t ko = so + ks * 32;             // 16 halves = 32 bytes
            uint32_t a[4][4], b[4][2], tb[4];
#pragma unroll
            for (int mi = 0; mi < 4; ++mi)
                ldsm_x4(a[mi], baseA[mi] + ko);
#pragma unroll
            for (int p = 0; p < 2; ++p) {
                ldsm_x4(tb, baseB[p] + ko);
                b[2*p][0]   = tb[0]; b[2*p][1]   = tb[1];
                b[2*p+1][0] = tb[2]; b[2*p+1][1] = tb[3];
            }
#pragma unroll
            for (int mi = 0; mi < 4; ++mi)
#pragma unroll
                for (int ni = 0; ni < 4; ++ni)
                    mma_f16(acc[mi][ni], a[mi], b[ni]);
        }
    }

    // ---------------- epilogue ----------------
    float c1v[8], c2v[8];
#pragma unroll
    for (int ni = 0; ni < 4; ++ni) {
        int n = n0 + n_off + ni * 8 + 2 * tg;
        if (EPI != 2) {
            c1v[ni * 2]     = c1[n];     c2v[ni * 2]     = c2[n];
            c1v[ni * 2 + 1] = c1[n + 1]; c2v[ni * 2 + 1] = c2[n + 1];
        } else {
            c2v[ni * 2]     = bias[n];
            c2v[ni * 2 + 1] = bias[n + 1];
        }
    }

#pragma unroll
    for (int mi = 0; mi < 4; ++mi) {
        const int r0 = m0 + m_off + mi * 16 + g;
        const int r1 = r0 + 8;
        float rr0 = 0.f, rm0 = 0.f, rr1 = 0.f, rm1 = 0.f;
        if (EPI != 2) {
            float2 s0 = stats[r0], s1 = stats[r1];
            if (SMODE == 1) {
                float m0v = s0.x * (1.f / Eq);
                float v0v = s0.y * (1.f / Eq) - m0v * m0v;
                float m1v = s1.x * (1.f / Eq);
                float v1v = s1.y * (1.f / Eq) - m1v * m1v;
                rr0 = rsqrtf(v0v + EPSq); rm0 = m0v * rr0;
                rr1 = rsqrtf(v1v + EPSq); rm1 = m1v * rr1;
            } else {
                rr0 = s0.y; rm0 = s0.x * s0.y;
                rr1 = s1.y; rm1 = s1.x * s1.y;
            }
        }
        float rs0 = 0.f, rq0 = 0.f, rs1 = 0.f, rq1 = 0.f;
#pragma unroll
        for (int ni = 0; ni < 4; ++ni) {
            const int n = n0 + n_off + ni * 8 + 2 * tg;
            float v0 = acc[mi][ni][0], v1 = acc[mi][ni][1];
            float v2 = acc[mi][ni][2], v3 = acc[mi][ni][3];
            if (EPI == 0 || EPI == 1) {
                v0 = rr0 * v0 - rm0 * c1v[ni * 2]     + c2v[ni * 2];
                v1 = rr0 * v1 - rm0 * c1v[ni * 2 + 1] + c2v[ni * 2 + 1];
                v2 = rr1 * v2 - rm1 * c1v[ni * 2]     + c2v[ni * 2];
                v3 = rr1 * v3 - rm1 * c1v[ni * 2 + 1] + c2v[ni * 2 + 1];
                if (EPI == 1) {
                    v0 = 0.5f * v0 * (1.f + erff(v0 * 0.70710678118654752f));
                    v1 = 0.5f * v1 * (1.f + erff(v1 * 0.70710678118654752f));
                    v2 = 0.5f * v2 * (1.f + erff(v2 * 0.70710678118654752f));
                    v3 = 0.5f * v3 * (1.f + erff(v3 * 0.70710678118654752f));
                }
            } else {
                if (RH) {
                    float2 ra = __half22float2(*(const __half2*)(residh + (size_t)r0 * N + n));
                    float2 rb = __half22float2(*(const __half2*)(residh + (size_t)r1 * N + n));
                    v0 += c2v[ni * 2] + ra.x;  v1 += c2v[ni * 2 + 1] + ra.y;
                    v2 += c2v[ni * 2] + rb.x;  v3 += c2v[ni * 2 + 1] + rb.y;
                } else {
                    const float2 ra = *(const float2*)(resid + (size_t)r0 * N + n);
                    const float2 rb = *(const float2*)(resid + (size_t)r1 * N + n);
                    v0 += c2v[ni * 2] + ra.x;  v1 += c2v[ni * 2 + 1] + ra.y;
                    v2 += c2v[ni * 2] + rb.x;  v3 += c2v[ni * 2 + 1] + rb.y;
                }
            }
            if (SACC) {
                rs0 += v0 + v1;           rq0 += v0 * v0 + v1 * v1;
                rs1 += v2 + v3;           rq1 += v2 * v2 + v3 * v3;
            }
            if (WF) {
                *(float2*)(Cf + (size_t)r0 * N + n) = make_float2(v0, v1);
                *(float2*)(Cf + (size_t)r1 * N + n) = make_float2(v2, v3);
            }
            if (WH) {
                *(__half2*)(Ch + (size_t)r0 * N + n) = __floats2half2_rn(v0, v1);
                *(__half2*)(Ch + (size_t)r1 * N + n) = __floats2half2_rn(v2, v3);
            }
        }
        if (SACC) {
#pragma unroll
            for (int o = 1; o <= 2; o <<= 1) {
                rs0 += __shfl_xor_sync(0xffffffffu, rs0, o);
                rq0 += __shfl_xor_sync(0xffffffffu, rq0, o);
                rs1 += __shfl_xor_sync(0xffffffffu, rs1, o);
                rq1 += __shfl_xor_sync(0xffffffffu, rq1, o);
            }
            if (tg == 0) {
                atomicAdd(&sums[r0].x, rs0);
                atomicAdd(&sums[r0].y, rq0);
                atomicAdd(&sums[r1].x, rs1);
                atomicAdd(&sums[r1].y, rq1);
            }
        }
    }
}

// ---------------- attention over batch axis (len 8) per (s, head) -----------
#define QSH 1160    // halves; 2320 B row stride
__global__ void __launch_bounds__(288) attn_k(const __half* __restrict__ qkv,
                                              __half* __restrict__ o) {
    __shared__ __half sq[8 * QSH];
    __shared__ float sc[8][64];
    const int s   = blockIdx.x;
    const int tid = threadIdx.x;

#pragma unroll
    for (int j = 0; j < 4; ++j) {            // 8 rows x 144 uint4 = 1152 loads
        int i = tid + j * 288;
        int b = i / 144, jj = i % 144;
        uint4 v = *(const uint4*)(qkv + ((size_t)(b * Sq + s)) * NQKV + jj * 8);
        *(uint4*)(sq + b * QSH + jj * 8) = v;
    }
    __syncthreads();

    const int h = tid >> 5, lane = tid & 31;
    if (h >= 8) return;
    const float scale = 0.14433756729740644f;   // 1/sqrt(48)

    {
        int idx0 = lane, idx1 = lane + 32;
        int b0 = idx0 >> 3, cc0 = idx0 & 7;
        int b1 = idx1 >> 3, cc1 = idx1 & 7;
        const __half2* q0 = (const __half2*)(sq + b0 * QSH + h * 48);
        const __half2* k0 = (const __half2*)(sq + cc0 * QSH + 384 + h * 48);
        const __half2* q1 = (const __half2*)(sq + b1 * QSH + h * 48);
        const __half2* k1 = (const __half2*)(sq + cc1 * QSH + 384 + h * 48);
        float s0 = 0.f, s1 = 0.f;
#pragma unroll
        for (int d2 = 0; d2 < 24; ++d2) {
            float2 qa = __half22float2(q0[d2]), ka = __half22float2(k0[d2]);
            s0 += qa.x * ka.x + qa.y * ka.y;
            float2 qb = __half22float2(q1[d2]), kb = __half22float2(k1[d2]);
            s1 += qb.x * kb.x + qb.y * kb.y;
        }
        sc[h][idx0] = s0 * scale;
        sc[h][idx1] = s1 * scale;
    }
    __syncwarp();

    if (lane < 8) {
        float e[8]; float mx = -1e30f;
#pragma unroll
        for (int c = 0; c < 8; ++c) { e[c] = sc[h][lane * 8 + c]; mx = fmaxf(mx, e[c]); }
        float sum = 0.f;
#pragma unroll
        for (int c = 0; c < 8; ++c) { e[c] = expf(e[c] - mx); sum += e[c]; }
        float inv = 1.f / sum;
#pragma unroll
        for (int c = 0; c < 8; ++c) sc[h][lane * 8 + c] = e[c] * inv;
    }
    __syncwarp();

#pragma unroll
    for (int j = 0; j < 3; ++j) {
        int e4 = lane + j * 32;
        int b = e4 / 12, d4 = e4 % 12;
        float a0 = 0.f, a1 = 0.f, a2 = 0.f, a3 = 0.f;
#pragma unroll
        for (int c = 0; c < 8; ++c) {
            float p = sc[h][b * 8 + c];
            const __half2* v = (const __half2*)(sq + c * QSH + 768 + h * 48 + d4 * 4);
            float2 f0 = __half22float2(v[0]);
            float2 f1 = __half22float2(v[1]);
            a0 += p * f0.x; a1 += p * f0.y; a2 += p * f1.x; a3 += p * f1.y;
        }
        __half2 o0 = __floats2half2_rn(a0, a1);
        __half2 o1 = __floats2half2_rn(a2, a3);
        __half2* dst = (__half2*)(o + ((size_t)(b * Sq + s)) * Eq + h * 48 + d4 * 4);
        dst[0] = o0; dst[1] = o1;
    }
}

// ---------------- launch -----------------------------------------------------
extern "C" void kernel_launch(void* const* d_in, const int* in_sizes, int n_in,
                              void* d_out, int out_size) {
    const float* x     = (const float*)d_in[0];
    const float* in_w  = (const float*)d_in[1];
    const float* in_b  = (const float*)d_in[2];
    const float* out_w = (const float*)d_in[3];
    const float* out_b = (const float*)d_in[4];
    const float* ln1g  = (const float*)d_in[5];
    const float* ln1b  = (const float*)d_in[6];
    const float* ln2g  = (const float*)d_in[7];
    const float* ln2b  = (const float*)d_in[8];
    const float* w1    = (const float*)d_in[9];
    const float* b1    = (const float*)d_in[10];
    const float* w2    = (const float*)d_in[11];
    const float* b2    = (const float*)d_in[12];
    float* out = (float*)d_out;

    float2 *stats, *sum2; float *c1q, *c2q, *c1f, *c2f;
    __half *xh, *qkv, *obuf, *x1h, *hbuf, *wqkv, *w1p, *owp, *w2p;
    cudaGetSymbolAddress((void**)&stats, g_stats);
    cudaGetSymbolAddress((void**)&sum2,  g_sum2);
    cudaGetSymbolAddress((void**)&xh,    g_xh);
    cudaGetSymbolAddress((void**)&qkv,   g_qkv);
    cudaGetSymbolAddress((void**)&obuf,  g_o);
    cudaGetSymbolAddress((void**)&x1h,   g_x1h);
    cudaGetSymbolAddress((void**)&hbuf,  g_h);
    cudaGetSymbolAddress((void**)&wqkv,  g_wqkv);
    cudaGetSymbolAddress((void**)&w1p,   g_w1p);
    cudaGetSymbolAddress((void**)&owp,   g_owp);
    cudaGetSymbolAddress((void**)&w2p,   g_w2p);
    cudaGetSymbolAddress((void**)&c1q,   g_c1q);
    cudaGetSymbolAddress((void**)&c2q,   g_c2q);
    cudaGetSymbolAddress((void**)&c1f,   g_c1f);
    cudaGetSymbolAddress((void**)&c2f,   g_c2f);

    cudaFuncSetAttribute((const void*)tc_gemm<0, true, false, false, 0, false>,
                         cudaFuncAttributeMaxDynamicSharedMemorySize, SMEM_GEMM);
    cudaFuncSetAttribute((const void*)tc_gemm<1, true, false, false, 1, false>,
                         cudaFuncAttributeMaxDynamicSharedMemorySize, SMEM_GEMM);
    cudaFuncSetAttribute((const void*)tc_gemm<2, true, false, true, 0, false>,
                         cudaFuncAttributeMaxDynamicSharedMemorySize, SMEM_GEMM);
    cudaFuncSetAttribute((const void*)tc_gemm<2, false, true, false, 0, true>,
                         cudaFuncAttributeMaxDynamicSharedMemorySize, SMEM_GEMM);

    // 0) fold LN1 into in_proj weights + LN2 into w1 (one launch)
    prep_all_k<<<NQKV + FFq, 128>>>(in_w, in_b, ln1g, ln1b, wqkv, c1q, c2q,
                                    w1,   b1,   ln2g, ln2b, w1p,  c1f, c2f);
    // 1) fp16-convert out_w + w2 (one launch)
    cvt_both_k<<<(OW_N + W2_N + 255) / 256, 256>>>(out_w, owp, w2, w2p);
    // 2) LN1 stats + x -> fp16 + zero LN2 sums
    stats_cvt_k<<<MROWS / 8, 256>>>(x, stats, xh, sum2);
    // 3) qkv = LN1(x) @ in_proj_w^T + in_proj_b   (LN folded, fp16 out)
    {
        dim3 g(NQKV / 128, MROWS / 128);
        tc_gemm<0, true, false, false, 0, false><<<g, 256, SMEM_GEMM>>>(
            xh, wqkv, nullptr, nullptr, nullptr, stats, c1q, c2q,
            nullptr, qkv, nullptr, Eq, NQKV);
    }
    // 4) batch-axis attention per (s, head)
    attn_k<<<Sq, 288>>>(qkv, obuf);
    // 5) x1h = fp16( x + o @ out_w^T + out_b ), accumulate LN2 sums
    {
        dim3 g(Eq / 128, MROWS / 128);
        tc_gemm<2, true, false, true, 0, false><<<g, 256, SMEM_GEMM>>>(
            obuf, owp, out_b, x, nullptr, nullptr, nullptr, nullptr,
            nullptr, x1h, sum2, Eq, Eq);
    }
    // 6) h = gelu( LN2(x1) @ w1^T + b1 )  (LN folded, stats from raw sums)
    {
        dim3 g(FFq / 128, MROWS / 128);
        tc_gemm<1, true, false, false, 1, false><<<g, 256, SMEM_GEMM>>>(
            x1h, w1p, nullptr, nullptr, nullptr, sum2, c1f, c2f,
            nullptr, hbuf, nullptr, Eq, FFq);
    }
    // 7) out = x1h + h @ w2^T + b2   (fp32 out, fp16 residual)
    {
        dim3 g(Eq / 128, MROWS / 128);
        tc_gemm<2, false, true, false, 0, true><<<g, 256, SMEM_GEMM>>>(
            hbuf, w2p, b2, nullptr, x1h, nullptr, nullptr, nullptr,
            out, nullptr, nullptr, FFq, Eq);
    }
}